// round 9
// baseline (speedup 1.0000x reference)
#include <cuda_runtime.h>

#define POOLK 7
#define NBINS (POOLK * POOLK)
#define NUM_ROIS 300
#define FH 50
#define FW 50
#define FC 512
#define NBIN_TOT (NUM_ROIS * NBINS)          // 14700
#define TOTAL_F4 (NBIN_TOT * (FC / 4))       // 1,881,600
#define F4_PER_THR 4
#define WRITE_THREADS (TOTAL_F4 / F4_PER_THR)  // 470,400

// Scratch (no cudaMalloc allowed)
__device__ float g_fmax[FH * FW];
__device__ float g_binmax[NBIN_TOT];

// K1: 2 pixels per 128-thread block; each thread loads 2 float4 (MLP=2).
// 64 threads (2 warps) cooperate per pixel.
__global__ void fmax_kernel(const float* __restrict__ fm) {
    __shared__ float smem[2][2];
    int tid = threadIdx.x;
    int half = tid >> 6;          // which pixel in this block
    int lt = tid & 63;            // lane within pixel group
    int pix = blockIdx.x * 2 + half;
    const float4* p = reinterpret_cast<const float4*>(fm + (size_t)pix * FC);
    float4 a = p[lt];
    float4 b = p[lt + 64];
    float m = fmaxf(fmaxf(fmaxf(a.x, a.y), fmaxf(a.z, a.w)),
                    fmaxf(fmaxf(b.x, b.y), fmaxf(b.z, b.w)));
#pragma unroll
    for (int off = 16; off > 0; off >>= 1)
        m = fmaxf(m, __shfl_xor_sync(0xffffffffu, m, off));
    if ((tid & 31) == 0) smem[half][lt >> 5] = m;
    __syncthreads();
    if (lt == 0) g_fmax[pix] = fmaxf(smem[half][0], smem[half][1]);
}

// K2: one thread per (roi, bin); g_fmax staged into smem first so the
// per-bin reduction loop has no long-scoreboard stalls.
__global__ void __launch_bounds__(256) binmax_kernel(
    const float* __restrict__ rois) {
    __shared__ float sf[FH * FW];
    int tid = threadIdx.x;
    for (int k = tid; k < FH * FW; k += 256) sf[k] = g_fmax[k];
    __syncthreads();

    int idx = blockIdx.x * 256 + tid;
    if (idx >= NBIN_TOT) return;

    int r = idx / NBINS;
    int bin = idx - r * NBINS;
    int i = bin / POOLK;
    int j = bin - i * POOLK;

    const float* roi = rois + r * 5;
    // reference: (rois * (1/16)).astype(int32) -> truncation; inputs >= 0
    int x1 = (int)(__ldg(roi + 1) * 0.0625f);
    int y1 = (int)(__ldg(roi + 2) * 0.0625f);
    int x2 = (int)(__ldg(roi + 3) * 0.0625f);
    int y2 = (int)(__ldg(roi + 4) * 0.0625f);
    int rh = y2 - y1 + 1;
    int rw = x2 - x1 + 1;

    int hs = min(max(y1 + (i * rh) / POOLK, 0), FH);
    int he = min(max(y1 + ((i + 1) * rh + POOLK - 1) / POOLK, 0), FH);
    int ws = min(max(x1 + (j * rw) / POOLK, 0), FW);
    int we = min(max(x1 + ((j + 1) * rw + POOLK - 1) / POOLK, 0), FW);

    float m = -INFINITY;
    for (int y = hs; y < he; y++) {
        const float* row = sf + y * FW;
        for (int x = ws; x < we; x++)
            m = fmaxf(m, row[x]);
    }
    g_binmax[idx] = m;
}

// K3: pure broadcast write. Thread t writes 4 consecutive float4 of bin
// t>>5 (uniform per warp -> one broadcast L2 sector per warp).
__global__ void __launch_bounds__(256) write_kernel(float* __restrict__ out) {
    int t = blockIdx.x * 256 + threadIdx.x;
    if (t >= WRITE_THREADS) return;
    float v = g_binmax[t >> 5];
    float4 vv = make_float4(v, v, v, v);
    float4* o = reinterpret_cast<float4*>(out) + (size_t)t * F4_PER_THR;
#pragma unroll
    for (int k = 0; k < F4_PER_THR; k++) o[k] = vv;
}

extern "C" void kernel_launch(void* const* d_in, const int* in_sizes, int n_in,
                              void* d_out, int out_size) {
    const float* rois = (const float*)d_in[0];          // (300, 5)
    const float* feature_maps = (const float*)d_in[1];  // (50, 50, 512)
    float* out = (float*)d_out;                         // (300, 7, 7, 512)

    fmax_kernel<<<(FH * FW) / 2, 128>>>(feature_maps);
    binmax_kernel<<<(NBIN_TOT + 255) / 256, 256>>>(rois);
    write_kernel<<<(WRITE_THREADS + 255) / 256, 256>>>(out);
}

// round 10
// speedup vs baseline: 1.2548x; 1.2548x over previous
#include <cuda_runtime.h>

#define POOLK 7
#define NBINS (POOLK * POOLK)        // 49
#define NUM_ROIS 300
#define FH 50
#define FW 50
#define FC 512
#define NPIX (FH * FW)               // 2500
#define THREADS 256
#define WARPS_PER_CTA (THREADS / 32) // 8
#define TOTAL_WARPS (NUM_ROIS * WARPS_PER_CTA) // 2400
#define F4_PER_ROI (NBINS * FC / 4)  // 6272

// Scratch + barrier state (no cudaMalloc allowed; zero-initialized)
__device__ float g_fmax[NPIX];
__device__ unsigned g_ctr = 0;
__device__ volatile unsigned g_gen = 0;

__global__ void __launch_bounds__(THREADS) fused_roi_kernel(
    const float* __restrict__ rois,
    const float* __restrict__ fm,
    float* __restrict__ out)
{
    __shared__ float sf[NPIX];
    __shared__ float sbin[NBINS];
    int tid = threadIdx.x;
    int r = blockIdx.x;                       // one ROI per CTA
    int lane = tid & 31;
    int gwarp = r * WARPS_PER_CTA + (tid >> 5);

    // ---- Phase 1: channel-max per pixel, 1 warp/pixel (2400 warps, 2500 px)
    for (int pix = gwarp; pix < NPIX; pix += TOTAL_WARPS) {
        const float4* p = reinterpret_cast<const float4*>(fm + (size_t)pix * FC);
        float4 a = p[lane];
        float4 b = p[lane + 32];
        float4 c = p[lane + 64];
        float4 d = p[lane + 96];
        float m = fmaxf(fmaxf(fmaxf(a.x, a.y), fmaxf(a.z, a.w)),
                        fmaxf(fmaxf(b.x, b.y), fmaxf(b.z, b.w)));
        m = fmaxf(m, fmaxf(fmaxf(fmaxf(c.x, c.y), fmaxf(c.z, c.w)),
                           fmaxf(fmaxf(d.x, d.y), fmaxf(d.z, d.w))));
#pragma unroll
        for (int off = 16; off > 0; off >>= 1)
            m = fmaxf(m, __shfl_xor_sync(0xffffffffu, m, off));
        if (lane == 0) g_fmax[pix] = m;
    }
    __syncthreads();

    // ---- Grid-wide barrier (all 300 CTAs co-resident; replay-safe:
    //      g_gen grows monotonically, g_ctr resets each launch)
    if (tid == 0) {
        __threadfence();                       // publish g_fmax writes
        unsigned g = g_gen;
        if (atomicAdd(&g_ctr, 1u) == NUM_ROIS - 1) {
            g_ctr = 0;
            __threadfence();
            g_gen = g + 1;                     // release
        } else {
            while (g_gen == g) __nanosleep(128);
            __threadfence();                   // acquire-ish
        }
    }
    __syncthreads();

    // ---- Phase 2: stage full fmax map into shared memory (L2 hits)
    for (int k = tid; k < NPIX; k += THREADS)
        sf[k] = __ldcg(&g_fmax[k]);
    __syncthreads();

    // ---- Phase 3: threads 0..48 compute one bin each from smem
    if (tid < NBINS) {
        int i = tid / POOLK;
        int j = tid - i * POOLK;
        const float* roi = rois + r * 5;
        // reference: (rois * (1/16)).astype(int32) -> truncation; inputs >= 0
        int x1 = (int)(__ldg(roi + 1) * 0.0625f);
        int y1 = (int)(__ldg(roi + 2) * 0.0625f);
        int x2 = (int)(__ldg(roi + 3) * 0.0625f);
        int y2 = (int)(__ldg(roi + 4) * 0.0625f);
        int rh = y2 - y1 + 1;
        int rw = x2 - x1 + 1;

        int hs = min(max(y1 + (i * rh) / POOLK, 0), FH);
        int he = min(max(y1 + ((i + 1) * rh + POOLK - 1) / POOLK, 0), FH);
        int ws = min(max(x1 + (j * rw) / POOLK, 0), FW);
        int we = min(max(x1 + ((j + 1) * rw + POOLK - 1) / POOLK, 0), FW);

        float m = -INFINITY;
        for (int y = hs; y < he; y++) {
            const float* row = sf + y * FW;
            for (int x = ws; x < we; x++)
                m = fmaxf(m, row[x]);
        }
        sbin[tid] = m;
    }
    __syncthreads();

    // ---- Phase 4: interleaved coalesced write of 49*512 floats (100 KB)
    //      k>>7 is uniform per warp -> LDS broadcast; STG.128 fully coalesced
    float4* o = reinterpret_cast<float4*>(out) + (size_t)r * F4_PER_ROI;
#pragma unroll 2
    for (int k = tid; k < F4_PER_ROI; k += THREADS) {
        float v = sbin[k >> 7];
        o[k] = make_float4(v, v, v, v);
    }
}

extern "C" void kernel_launch(void* const* d_in, const int* in_sizes, int n_in,
                              void* d_out, int out_size) {
    const float* rois = (const float*)d_in[0];          // (300, 5)
    const float* feature_maps = (const float*)d_in[1];  // (50, 50, 512)
    float* out = (float*)d_out;                         // (300, 7, 7, 512)

    fused_roi_kernel<<<NUM_ROIS, THREADS>>>(rois, feature_maps, out);
}

// round 11
// speedup vs baseline: 1.2765x; 1.0173x over previous
#include <cuda_runtime.h>

#define POOLK 7
#define NBINS (POOLK * POOLK)
#define NUM_ROIS 300
#define FH 50
#define FW 50
#define FC 512
#define NPIX (FH * FW)
#define NBIN_TOT (NUM_ROIS * NBINS)            // 14700
#define TOTAL_F4 (NBIN_TOT * (FC / 4))         // 1,881,600 = 7350 * 256

// Scratch (no cudaMalloc allowed)
__device__ float g_fmax[NPIX];
__device__ float g_binmax[NBIN_TOT];

// K1: one warp per pixel, max over 512 contiguous channels (MLP=4/thread).
__global__ void fmax_kernel(const float* __restrict__ fm) {
    int warp = (blockIdx.x * blockDim.x + threadIdx.x) >> 5;
    int lane = threadIdx.x & 31;
    if (warp >= NPIX) return;
    const float4* p = reinterpret_cast<const float4*>(fm + (size_t)warp * FC);
    float m = -INFINITY;
#pragma unroll
    for (int k = 0; k < 4; k++) {
        float4 v = p[lane + 32 * k];
        m = fmaxf(m, fmaxf(fmaxf(v.x, v.y), fmaxf(v.z, v.w)));
    }
#pragma unroll
    for (int off = 16; off > 0; off >>= 1)
        m = fmaxf(m, __shfl_xor_sync(0xffffffffu, m, off));
    if (lane == 0) g_fmax[warp] = m;
}

// K2: one thread per (roi, bin); g_fmax staged into smem first so the
// per-bin reduction is an LDS chain (4 cyc/step), not L2 loads (234 cyc).
__global__ void __launch_bounds__(256) binmax_kernel(
    const float* __restrict__ rois) {
    __shared__ float sf[NPIX];
    int tid = threadIdx.x;
#pragma unroll
    for (int k = tid; k < NPIX; k += 256) sf[k] = g_fmax[k];
    __syncthreads();

    int idx = blockIdx.x * 256 + tid;
    if (idx >= NBIN_TOT) return;

    int r = idx / NBINS;
    int bin = idx - r * NBINS;
    int i = bin / POOLK;
    int j = bin - i * POOLK;

    const float* roi = rois + r * 5;
    // reference: (rois * (1/16)).astype(int32) -> truncation; inputs >= 0
    int x1 = (int)(__ldg(roi + 1) * 0.0625f);
    int y1 = (int)(__ldg(roi + 2) * 0.0625f);
    int x2 = (int)(__ldg(roi + 3) * 0.0625f);
    int y2 = (int)(__ldg(roi + 4) * 0.0625f);
    int rh = y2 - y1 + 1;
    int rw = x2 - x1 + 1;

    int hs = min(max(y1 + (i * rh) / POOLK, 0), FH);
    int he = min(max(y1 + ((i + 1) * rh + POOLK - 1) / POOLK, 0), FH);
    int ws = min(max(x1 + (j * rw) / POOLK, 0), FW);
    int we = min(max(x1 + ((j + 1) * rw + POOLK - 1) / POOLK, 0), FW);

    float m = -INFINITY;
    for (int y = hs; y < he; y++) {
        const float* row = sf + y * FW;
        for (int x = ws; x < we; x++)
            m = fmaxf(m, row[x]);
    }
    g_binmax[idx] = m;
}

// K3: minimal write kernel. Thread t: one uniform-per-warp load (t>>7 is
// constant across the warp -> 1 broadcast sector) + one interleaved,
// fully-coalesced STG.128. 1,881,600 threads exactly.
__global__ void __launch_bounds__(256) write_kernel(float* __restrict__ out) {
    int t = blockIdx.x * 256 + threadIdx.x;
    float v = __ldg(&g_binmax[t >> 7]);
    reinterpret_cast<float4*>(out)[t] = make_float4(v, v, v, v);
}

extern "C" void kernel_launch(void* const* d_in, const int* in_sizes, int n_in,
                              void* d_out, int out_size) {
    const float* rois = (const float*)d_in[0];          // (300, 5)
    const float* feature_maps = (const float*)d_in[1];  // (50, 50, 512)
    float* out = (float*)d_out;                         // (300, 7, 7, 512)

    fmax_kernel<<<(NPIX * 32 + 255) / 256, 256>>>(feature_maps);
    binmax_kernel<<<(NBIN_TOT + 255) / 256, 256>>>(rois);
    write_kernel<<<TOTAL_F4 / 256, 256>>>(out);
}